// round 3
// baseline (speedup 1.0000x reference)
#include <cuda_runtime.h>
#include <cub/cub.cuh>
#include <thrust/iterator/counting_iterator.h>
#include <thrust/iterator/transform_iterator.h>
#include <cstdint>

// Problem max sizes: E_e=500K, E_a=1M -> E=1.5M. Reserve a little headroom.
static constexpr int MAX_E = 1600000;

// Scratch (allocation-free: __device__ globals)
__device__ uint32_t g_keys_a[MAX_E];
__device__ uint32_t g_keys_b[MAX_E];
__device__ uint32_t g_vals_a[MAX_E];
__device__ uint32_t g_vals_b[MAX_E];
__device__ int      g_sums[MAX_E];
__device__ uint32_t g_segflag[MAX_E];      // per ORIGINAL edge: (seg<<1)|is_leader
__device__ unsigned char g_cub_temp[64 * 1024 * 1024];

// ---------------------------------------------------------------------------
// packed f32x2 FMA: acc.{lo,hi} += a * w.{lo,hi}
__device__ __forceinline__ void ffma2(unsigned long long& acc, float a,
                                      unsigned long long w) {
    unsigned long long aa;
    asm("mov.b64 %0, {%1, %1};" : "=l"(aa) : "f"(a));
    asm("fma.rn.f32x2 %0, %1, %2, %0;" : "+l"(acc) : "l"(aa), "l"(w));
}

// 1. build 32-bit sort keys: (row<<16)|col, payload = original edge id
__global__ void k_build_keys(const int* __restrict__ ei, const int* __restrict__ ai,
                             int Ee, int Ea) {
    int E = Ee + Ea;
    int i = blockIdx.x * blockDim.x + threadIdx.x;
    if (i >= E) return;
    int r, c;
    if (i < Ee) { r = ei[i];          c = ei[Ee + i]; }
    else        { int j = i - Ee; r = ai[j]; c = ai[Ea + j]; }
    g_keys_a[i] = ((uint32_t)r << 16) | (uint32_t)c;
    g_vals_a[i] = (uint32_t)i;
}

// flag(i) = is segment leader in sorted order (computed on the fly, no g_flags)
struct FlagOp {
    __host__ __device__ __forceinline__ int operator()(int i) const {
#ifdef __CUDA_ARCH__
        return (i == 0) || (g_keys_b[i] != g_keys_b[i - 1]);
#else
        return 0;
#endif
    }
};

// 3. inverse map: original edge id -> (segment id, leader flag)
__global__ void k_invmap(int E) {
    int i = blockIdx.x * blockDim.x + threadIdx.x;
    if (i >= E) return;
    int flag = (i == 0) || (g_keys_b[i] != g_keys_b[i - 1]);
    uint32_t orig = g_vals_b[i];
    g_segflag[orig] = ((uint32_t)(g_sums[i] - 1) << 1) | (uint32_t)flag;
}

// 4. leader scatter: WARP per edge. W held in registers (lane owns output
//    cols 2l, 2l+1 as 32 packed f32x2 regs). a-vector read via warp-uniform
//    LDG.128 broadcast. One coalesced STG.64 covers the 256B output row.
__global__ void __launch_bounds__(256, 2)
k_scatter_leaders(const int* __restrict__ ei,
                  const float* __restrict__ eattr,
                  const int* __restrict__ ai,
                  const float* __restrict__ aattr,
                  const float* __restrict__ W,
                  float* __restrict__ out, int Ee, int Ea) {
    const int E = Ee + Ea;
    float* out_r    = out;
    float* out_c    = out + E;
    float* out_attr = out + 2 * (size_t)E;

    const int lane = threadIdx.x & 31;

    // per-lane W: rows (2*lane) and (2*lane+1), packed as f32x2 per k
    unsigned long long w2[32];
    #pragma unroll
    for (int k = 0; k < 32; k++) {
        float x = __ldg(&W[(2 * lane) * 32 + k]);
        float y = __ldg(&W[(2 * lane + 1) * 32 + k]);
        asm("mov.b64 %0, {%1, %2};" : "=l"(w2[k]) : "f"(x), "f"(y));
    }

    int warp   = (blockIdx.x * blockDim.x + threadIdx.x) >> 5;
    int nwarps = (gridDim.x * blockDim.x) >> 5;

    for (int e = warp; e < E; e += nwarps) {
        uint32_t sf = g_segflag[e];                  // warp-uniform load
        if (!(sf & 1u)) continue;                    // not a leader (rare)
        int seg = (int)(sf >> 1);

        float2 v;
        if (e < Ee) {
            v = reinterpret_cast<const float2*>(eattr + (size_t)e * 64)[lane];
        } else {
            const float4* a4 =
                reinterpret_cast<const float4*>(aattr + (size_t)(e - Ee) * 32);
            unsigned long long acc = 0ull;           // (+0.0f, +0.0f)
            #pragma unroll
            for (int kg = 0; kg < 8; kg++) {
                float4 av = __ldg(a4 + kg);          // uniform -> broadcast
                ffma2(acc, av.x, w2[4 * kg + 0]);
                ffma2(acc, av.y, w2[4 * kg + 1]);
                ffma2(acc, av.z, w2[4 * kg + 2]);
                ffma2(acc, av.w, w2[4 * kg + 3]);
            }
            asm("mov.b64 {%0, %1}, %2;" : "=f"(v.x), "=f"(v.y) : "l"(acc));
        }
        reinterpret_cast<float2*>(out_attr + (size_t)seg * 64)[lane] = v;

        if (lane == 0) {
            int r, c;
            if (e < Ee) { r = ei[e];          c = ei[Ee + e]; }
            else        { int j = e - Ee; r = ai[j]; c = ai[Ea + j]; }
            out_r[seg] = (float)r;
            out_c[seg] = (float)c;
        }
    }
}

// 5. duplicate scatter: ~450 of 1.5M edges; runs AFTER leaders (stream order).
__global__ void k_scatter_dups(const float* __restrict__ eattr,
                               const float* __restrict__ aattr,
                               const float* __restrict__ W,
                               float* __restrict__ out, int Ee, int Ea) {
    int E = Ee + Ea;
    int e = blockIdx.x * blockDim.x + threadIdx.x;
    if (e >= E) return;
    uint32_t sf = g_segflag[e];
    if (sf & 1u) return;                    // leader -> nothing to do
    int seg = (int)(sf >> 1);
    float* orow = out + 2 * (size_t)E + (size_t)seg * 64;
    if (e < Ee) {
        const float* a = eattr + (size_t)e * 64;
        for (int j = 0; j < 64; j++) atomicAdd(orow + j, a[j]);
    } else {
        const float* a = aattr + (size_t)(e - Ee) * 32;
        float av[32];
        #pragma unroll
        for (int k = 0; k < 32; k++) av[k] = a[k];
        for (int j = 0; j < 64; j++) {
            float s = 0.f;
            #pragma unroll
            for (int k = 0; k < 32; k++) s += av[k] * W[j * 32 + k];
            atomicAdd(orow + j, s);
        }
    }
}

// 6. tail: pad region [num_unique, E): r/c <- -1, attrs <- 0; write num_unique
__global__ void k_tail(float* __restrict__ out, int E) {
    int nu = g_sums[E - 1];
    int stride = gridDim.x * blockDim.x;
    for (int i = nu + blockIdx.x * blockDim.x + threadIdx.x; i < E; i += stride) {
        out[i]     = -1.0f;   // uniq_r pad
        out[E + i] = -1.0f;   // uniq_c pad
    }
    float* out_attr = out + 2 * (size_t)E;
    size_t start = (size_t)nu * 64;
    size_t end   = (size_t)E * 64;
    for (size_t i = start + blockIdx.x * blockDim.x + threadIdx.x; i < end;
         i += (size_t)stride)
        out_attr[i] = 0.0f;
    if (blockIdx.x == 0 && threadIdx.x == 0)
        out[2 * (size_t)E + (size_t)E * 64] = (float)nu;
}

// ---------------------------------------------------------------------------
extern "C" void kernel_launch(void* const* d_in, const int* in_sizes, int n_in,
                              void* d_out, int out_size) {
    (void)n_in; (void)out_size;
    const int*   ei    = (const int*)d_in[0];     // edge_index  (2, E_e)
    const float* eattr = (const float*)d_in[1];   // edge_attr   (E_e, 64)
    const int*   ai    = (const int*)d_in[2];     // arrwp_index (2, E_a)
    const float* aattr = (const float*)d_in[3];   // arrwp_attr  (E_a, 32)
    const float* W     = (const float*)d_in[4];   // W           (64, 32)
    const int Ee = in_sizes[0] / 2;
    const int Ea = in_sizes[2] / 2;
    const int E  = Ee + Ea;
    float* out = (float*)d_out;

    void *pka, *pkb, *pva, *pvb, *ps, *ptmp;
    cudaGetSymbolAddress(&pka, g_keys_a);
    cudaGetSymbolAddress(&pkb, g_keys_b);
    cudaGetSymbolAddress(&pva, g_vals_a);
    cudaGetSymbolAddress(&pvb, g_vals_b);
    cudaGetSymbolAddress(&ps,  g_sums);
    cudaGetSymbolAddress(&ptmp, g_cub_temp);

    const int T = 256;
    k_build_keys<<<(E + T - 1) / T, T>>>(ei, ai, Ee, Ea);

    size_t tb = sizeof(g_cub_temp);
    cub::DeviceRadixSort::SortPairs(ptmp, tb,
                                    (const uint32_t*)pka, (uint32_t*)pkb,
                                    (const uint32_t*)pva, (uint32_t*)pvb,
                                    E, 0, 32);

    // segment ids: inclusive scan of on-the-fly boundary flags
    thrust::counting_iterator<int> cnt(0);
    auto flag_it = thrust::make_transform_iterator(cnt, FlagOp());
    size_t tb2 = sizeof(g_cub_temp);
    cub::DeviceScan::InclusiveSum(ptmp, tb2, flag_it, (int*)ps, E);

    k_invmap<<<(E + T - 1) / T, T>>>(E);
    k_scatter_leaders<<<2048, T>>>(ei, eattr, ai, aattr, W, out, Ee, Ea);
    k_scatter_dups<<<(E + T - 1) / T, T>>>(eattr, aattr, W, out, Ee, Ea);
    k_tail<<<256, T>>>(out, E);
}

// round 4
// speedup vs baseline: 2.9731x; 2.9731x over previous
#include <cuda_runtime.h>
#include <cub/cub.cuh>
#include <cstdint>

static constexpr int MAX_E = 1600000;
static constexpr int CHUNK = 256;                 // arrwp rows per pipeline stage

// Scratch (allocation-free: __device__ globals)
__device__ uint32_t g_keys_a[MAX_E];
__device__ uint32_t g_keys_b[MAX_E];
__device__ uint32_t g_vals_a[MAX_E];
__device__ uint32_t g_vals_b[MAX_E];
__device__ int      g_flags[MAX_E];
__device__ int      g_sums[MAX_E];
__device__ uint32_t g_segflag[MAX_E];             // per ORIGINAL edge: (seg<<1)|leader
__device__ unsigned char g_cub_temp[64 * 1024 * 1024];

// ---------------------------------------------------------------------------
__device__ __forceinline__ uint32_t smem_u32(const void* p) {
    uint32_t a;
    asm("{ .reg .u64 t; cvta.to.shared.u64 t, %1; cvt.u32.u64 %0, t; }"
        : "=r"(a) : "l"(p));
    return a;
}
__device__ __forceinline__ void fma2(unsigned long long& acc,
                                     unsigned long long a, unsigned long long b) {
    asm("fma.rn.f32x2 %0, %1, %2, %0;" : "+l"(acc) : "l"(a), "l"(b));
}
__device__ __forceinline__ void mbar_init(uint32_t mbar, uint32_t cnt) {
    asm volatile("mbarrier.init.shared.b64 [%0], %1;" :: "r"(mbar), "r"(cnt) : "memory");
}
__device__ __forceinline__ void mbar_expect_tx(uint32_t mbar, uint32_t bytes) {
    asm volatile("mbarrier.arrive.expect_tx.shared.b64 _, [%0], %1;"
                 :: "r"(mbar), "r"(bytes) : "memory");
}
__device__ __forceinline__ void mbar_wait(uint32_t mbar, uint32_t parity) {
    uint32_t done;
    asm volatile(
        "{ .reg .pred p; mbarrier.try_wait.parity.acquire.cta.shared::cta.b64 p, [%1], %2;"
        " selp.b32 %0, 1, 0, p; }"
        : "=r"(done) : "r"(mbar), "r"(parity) : "memory");
    if (!done) {
        asm volatile(
            "{ .reg .pred P1; WL%=:"
            " mbarrier.try_wait.parity.acquire.cta.shared::cta.b64 P1, [%0], %1, 0x989680;"
            " @P1 bra.uni WD%=; bra.uni WL%=; WD%=: }"
            :: "r"(mbar), "r"(parity) : "memory");
    }
}
__device__ __forceinline__ void bulk_copy(uint32_t dst, const void* src,
                                          uint32_t bytes, uint32_t mbar) {
    asm volatile(
        "cp.async.bulk.shared::cta.global.mbarrier::complete_tx::bytes [%0], [%1], %2, [%3];"
        :: "r"(dst), "l"(src), "r"(bytes), "r"(mbar) : "memory");
}

// ---------------------------------------------------------------------------
// 1. build 32-bit sort keys: (row<<16)|col, payload = original edge id
__global__ void k_build_keys(const int* __restrict__ ei, const int* __restrict__ ai,
                             int Ee, int Ea) {
    int E = Ee + Ea;
    int i = blockIdx.x * blockDim.x + threadIdx.x;
    if (i >= E) return;
    int r, c;
    if (i < Ee) { r = ei[i];          c = ei[Ee + i]; }
    else        { int j = i - Ee; r = ai[j]; c = ai[Ea + j]; }
    g_keys_a[i] = ((uint32_t)r << 16) | (uint32_t)c;
    g_vals_a[i] = (uint32_t)i;
}

// 2. segment-boundary flags on sorted keys
__global__ void k_flags(int E) {
    int i = blockIdx.x * blockDim.x + threadIdx.x;
    if (i >= E) return;
    g_flags[i] = (i == 0) || (g_keys_b[i] != g_keys_b[i - 1]);
}

// 3. inverse map: original edge id -> (segment id, leader flag)
__global__ void k_invmap(int E) {
    int i = blockIdx.x * blockDim.x + threadIdx.x;
    if (i >= E) return;
    uint32_t orig = g_vals_b[i];
    g_segflag[orig] = ((uint32_t)(g_sums[i] - 1) << 1) | (uint32_t)g_flags[i];
}

// 4. raw-edge copy: one thread per float4 -> maximal MLP, pure bandwidth.
__global__ void k_copy_edges(const int* __restrict__ ei,
                             const float* __restrict__ eattr,
                             float* __restrict__ out, int Ee, int E) {
    int i = blockIdx.x * blockDim.x + threadIdx.x;
    if (i >= Ee * 16) return;
    int e = i >> 4, f4 = i & 15;
    uint32_t sf = g_segflag[e];
    if (!(sf & 1u)) return;                       // non-leader (rare)
    int seg = (int)(sf >> 1);
    float4 v = reinterpret_cast<const float4*>(eattr)[i];
    float4* out_attr4 = reinterpret_cast<float4*>(out + 2 * (size_t)E);
    out_attr4[(size_t)seg * 16 + f4] = v;
    if (f4 == 0) {
        out[seg]     = (float)ei[e];
        out[E + seg] = (float)ei[Ee + e];
    }
}

// 5. arrwp projection+scatter: cp.async.bulk double-buffered staging of 256
//    contiguous rows/stage; warp-per-edge compute with register-resident W
//    (lane owns cols lane and lane+32; even/odd-k split => pure fma.rn.f32x2).
// SMEM layout (dynamic):
//   [0,16)        mbar[2]
//   [16, +2KB)    segflag stage 0/1   (256 x u32 each)
//   [2064, +2KB)  row ids stage 0/1
//   [4112, +2KB)  col ids stage 0/1   -> pad to 8192
//   [8192, +64KB) attr stage 0/1      (256 x 128B each)
static constexpr int SM_FLAG = 16;
static constexpr int SM_ROW  = SM_FLAG + 2 * CHUNK * 4;
static constexpr int SM_COL  = SM_ROW  + 2 * CHUNK * 4;
static constexpr int SM_ATTR = 8192;
static constexpr int SM_TOTAL = SM_ATTR + 2 * CHUNK * 128;

__global__ void __launch_bounds__(256, 2)
k_proj_arrwp(const int* __restrict__ ai, const float* __restrict__ aattr,
             const float* __restrict__ W, float* __restrict__ out,
             int Ee, int Ea) {
    extern __shared__ unsigned char sm[];
    const uint32_t sbase = smem_u32(sm);
    const int E = Ee + Ea;
    float* out_attr = out + 2 * (size_t)E;

    const int tid  = threadIdx.x;
    const int lane = tid & 31;
    const int wrp  = tid >> 5;

    // register W: col j=lane and j=lane+32, packed float2 over (2kk, 2kk+1)
    unsigned long long wa[16], wb[16];
    {
        const unsigned long long* Wa =
            reinterpret_cast<const unsigned long long*>(W + lane * 32);
        const unsigned long long* Wb =
            reinterpret_cast<const unsigned long long*>(W + (lane + 32) * 32);
        #pragma unroll
        for (int kk = 0; kk < 16; kk++) { wa[kk] = __ldg(Wa + kk); wb[kk] = __ldg(Wb + kk); }
    }

    const int nChunks = (Ea + CHUNK - 1) / CHUNK;
    if (tid == 0) { mbar_init(sbase + 0, 1); mbar_init(sbase + 8, 1); }
    __syncthreads();

    int c0 = blockIdx.x;
    if (c0 >= nChunks) return;

    auto issue = [&](int c, int s) {
        int base = c * CHUNK;
        int rem  = min(CHUNK, Ea - base);
        bool full = (rem == CHUNK);
        uint32_t attrB = (uint32_t)rem * 128u;
        uint32_t flagB = ((uint32_t)rem * 4u + 15u) & ~15u;   // headroom in g_segflag
        uint32_t tx = attrB + flagB + (full ? 2048u : 0u);
        uint32_t mb = sbase + s * 8;
        mbar_expect_tx(mb, tx);
        bulk_copy(sbase + SM_ATTR + s * (CHUNK * 128), aattr + (size_t)base * 32, attrB, mb);
        bulk_copy(sbase + SM_FLAG + s * (CHUNK * 4), &g_segflag[Ee + base], flagB, mb);
        if (full) {
            bulk_copy(sbase + SM_ROW + s * (CHUNK * 4), ai + base,      CHUNK * 4, mb);
            bulk_copy(sbase + SM_COL + s * (CHUNK * 4), ai + Ea + base, CHUNK * 4, mb);
        }
    };

    if (tid == 0) issue(c0, 0);
    int phase0 = 0, phase1 = 0;

    int li = 0;
    for (int c = c0; c < nChunks; c += gridDim.x, li++) {
        int s = li & 1;
        int cn = c + gridDim.x;
        if (tid == 0 && cn < nChunks) issue(cn, s ^ 1);

        mbar_wait(sbase + s * 8, s ? phase1 : phase0);
        if (s) phase1 ^= 1; else phase0 ^= 1;

        int base = c * CHUNK;
        int rem  = min(CHUNK, Ea - base);
        bool full = (rem == CHUNK);
        int lbase = wrp * 32;
        if (lbase < rem) {
            int cnt = min(32, rem - lbase);
            const uint32_t* flag_s = (const uint32_t*)(sm + SM_FLAG + s * (CHUNK * 4));
            const int* row_s = (const int*)(sm + SM_ROW + s * (CHUNK * 4));
            const int* col_s = (const int*)(sm + SM_COL + s * (CHUNK * 4));
            const float* attr_s = (const float*)(sm + SM_ATTR + s * (CHUNK * 128));

            uint32_t sfv = (lane < cnt) ? flag_s[lbase + lane] : 0u;
            int rv = 0, cv = 0;
            if (full) { rv = row_s[lbase + lane]; cv = col_s[lbase + lane]; }

            for (int t = 0; t < cnt; t++) {
                uint32_t sfe = __shfl_sync(0xFFFFFFFFu, sfv, t);
                int rr = full ? __shfl_sync(0xFFFFFFFFu, rv, t) : 0;
                int cc = full ? __shfl_sync(0xFFFFFFFFu, cv, t) : 0;
                if (!(sfe & 1u)) continue;                    // non-leader (rare)
                int seg = (int)(sfe >> 1);
                const unsigned long long* a2 =
                    (const unsigned long long*)(attr_s + (lbase + t) * 32);
                unsigned long long accA = 0ull, accB = 0ull;
                #pragma unroll
                for (int kk = 0; kk < 16; kk++) {
                    unsigned long long av = a2[kk];           // uniform LDS.64
                    fma2(accA, av, wa[kk]);
                    fma2(accB, av, wb[kk]);
                }
                float ax, ay, bx, by;
                asm("mov.b64 {%0, %1}, %2;" : "=f"(ax), "=f"(ay) : "l"(accA));
                asm("mov.b64 {%0, %1}, %2;" : "=f"(bx), "=f"(by) : "l"(accB));
                float* orow = out_attr + (size_t)seg * 64;
                orow[lane]      = ax + ay;
                orow[32 + lane] = bx + by;
                if (!full && lane == 0) {
                    int j = base + lbase + t;
                    rr = ai[j]; cc = ai[Ea + j];
                }
                if (lane == 0) {
                    out[seg]     = (float)rr;
                    out[E + seg] = (float)cc;
                }
            }
        }
        __syncthreads();   // buffer s free for re-issue two iterations later
    }
}

// 6. duplicate scatter: rare; runs AFTER leader kernels (stream order).
__global__ void k_scatter_dups(const float* __restrict__ eattr,
                               const float* __restrict__ aattr,
                               const float* __restrict__ W,
                               float* __restrict__ out, int Ee, int Ea) {
    int E = Ee + Ea;
    int e = blockIdx.x * blockDim.x + threadIdx.x;
    if (e >= E) return;
    uint32_t sf = g_segflag[e];
    if (sf & 1u) return;
    int seg = (int)(sf >> 1);
    float* orow = out + 2 * (size_t)E + (size_t)seg * 64;
    if (e < Ee) {
        const float* a = eattr + (size_t)e * 64;
        for (int j = 0; j < 64; j++) atomicAdd(orow + j, a[j]);
    } else {
        const float* a = aattr + (size_t)(e - Ee) * 32;
        float av[32];
        #pragma unroll
        for (int k = 0; k < 32; k++) av[k] = a[k];
        for (int j = 0; j < 64; j++) {
            float s = 0.f;
            #pragma unroll
            for (int k = 0; k < 32; k++) s += av[k] * W[j * 32 + k];
            atomicAdd(orow + j, s);
        }
    }
}

// 7. tail: pad region [num_unique, E): r/c <- -1, attrs <- 0; write num_unique
__global__ void k_tail(float* __restrict__ out, int E) {
    int nu = g_sums[E - 1];
    int stride = gridDim.x * blockDim.x;
    for (int i = nu + blockIdx.x * blockDim.x + threadIdx.x; i < E; i += stride) {
        out[i]     = -1.0f;
        out[E + i] = -1.0f;
    }
    float* out_attr = out + 2 * (size_t)E;
    size_t start = (size_t)nu * 64;
    size_t end   = (size_t)E * 64;
    for (size_t i = start + blockIdx.x * blockDim.x + threadIdx.x; i < end;
         i += (size_t)stride)
        out_attr[i] = 0.0f;
    if (blockIdx.x == 0 && threadIdx.x == 0)
        out[2 * (size_t)E + (size_t)E * 64] = (float)nu;
}

// ---------------------------------------------------------------------------
extern "C" void kernel_launch(void* const* d_in, const int* in_sizes, int n_in,
                              void* d_out, int out_size) {
    (void)n_in; (void)out_size;
    const int*   ei    = (const int*)d_in[0];
    const float* eattr = (const float*)d_in[1];
    const int*   ai    = (const int*)d_in[2];
    const float* aattr = (const float*)d_in[3];
    const float* W     = (const float*)d_in[4];
    const int Ee = in_sizes[0] / 2;
    const int Ea = in_sizes[2] / 2;
    const int E  = Ee + Ea;
    float* out = (float*)d_out;

    void *pka, *pkb, *pva, *pvb, *pf, *ps, *ptmp;
    cudaGetSymbolAddress(&pka, g_keys_a);
    cudaGetSymbolAddress(&pkb, g_keys_b);
    cudaGetSymbolAddress(&pva, g_vals_a);
    cudaGetSymbolAddress(&pvb, g_vals_b);
    cudaGetSymbolAddress(&pf,  g_flags);
    cudaGetSymbolAddress(&ps,  g_sums);
    cudaGetSymbolAddress(&ptmp, g_cub_temp);

    static bool attr_set = false;
    if (!attr_set) {
        cudaFuncSetAttribute(k_proj_arrwp,
                             cudaFuncAttributeMaxDynamicSharedMemorySize, SM_TOTAL);
        attr_set = true;
    }

    const int T = 256;
    k_build_keys<<<(E + T - 1) / T, T>>>(ei, ai, Ee, Ea);

    size_t tb = sizeof(g_cub_temp);
    cub::DeviceRadixSort::SortPairs(ptmp, tb,
                                    (const uint32_t*)pka, (uint32_t*)pkb,
                                    (const uint32_t*)pva, (uint32_t*)pvb,
                                    E, 0, 32);

    k_flags<<<(E + T - 1) / T, T>>>(E);

    size_t tb2 = sizeof(g_cub_temp);
    cub::DeviceScan::InclusiveSum(ptmp, tb2, (const int*)pf, (int*)ps, E);

    k_invmap<<<(E + T - 1) / T, T>>>(E);
    k_copy_edges<<<(Ee * 16 + T - 1) / T, T>>>(ei, eattr, out, Ee, E);
    k_proj_arrwp<<<296, T, SM_TOTAL>>>(ai, aattr, W, out, Ee, Ea);
    k_scatter_dups<<<(E + T - 1) / T, T>>>(eattr, aattr, W, out, Ee, Ea);
    k_tail<<<256, T>>>(out, E);
}